// round 1
// baseline (speedup 1.0000x reference)
#include <cuda_runtime.h>
#include <cuda_bf16.h>

// Problem constants (from reference):
//   B=4, N=512, M=512, ZD=128, YD=2, XD=1
// Inputs (metadata order): t (B,N,XD) f32, z (B,N,ZD) f32, x (B,M,XD) f32,
//                          sigma (ZD,) f32, W (YD,ZD) f32, b (YD,) f32
// Output: (B, M, YD) f32 = 4096 elements.
//
// Math: out[b,m,y] = b_y + sum_n sum_c W[y,c] * z[b,n,c] * exp(-0.5*((x_m - t_n)/exp(sigma_c))^2)
// Fast path (all sigma equal, which holds for the bench inputs):
//   out[b,m,y] = b_y + sum_n exp(coef * (x_m - t_n)^2) * zw[b,n,y],  zw = z @ W^T,
//   coef = -0.5 * exp(-2*sigma_0).
// General path (any sigma): per-channel exp, still correct, selected in-kernel.

#define BB 4
#define NN 512
#define MM 512
#define ZDIM 128
#define YDIM 2

// scratch: zw[b,n,y]  (4*512*2 = 4096 floats)
__device__ float g_zw[BB * NN * YDIM];

// ---------------------------------------------------------------------------
// Kernel 1: zw[b,n,y] = sum_c z[b,n,c] * W[y,c]
// ---------------------------------------------------------------------------
__global__ void prep_zw_kernel(const float* __restrict__ z,
                               const float* __restrict__ W) {
    int idx = blockIdx.x * blockDim.x + threadIdx.x;  // over B*N*YD = 4096
    if (idx >= BB * NN * YDIM) return;
    int y  = idx % YDIM;
    int bn = idx / YDIM;
    const float* zr = z + bn * ZDIM;
    const float* wr = W + y * ZDIM;
    float acc = 0.0f;
#pragma unroll 8
    for (int c = 0; c < ZDIM; ++c) acc = fmaf(zr[c], wr[c], acc);
    g_zw[idx] = acc;
}

// ---------------------------------------------------------------------------
// Kernel 2: main. One warp per (b, m) output point. 8 warps / block,
// all warps in a block share the same batch b -> t and zw staged in smem.
// ---------------------------------------------------------------------------
__global__ __launch_bounds__(256) void decoder_main_kernel(
    const float* __restrict__ t,
    const float* __restrict__ z,
    const float* __restrict__ x,
    const float* __restrict__ sigma,
    const float* __restrict__ W,
    const float* __restrict__ bias,
    float* __restrict__ out) {
    __shared__ float t_s[NN];
    __shared__ float zw0_s[NN];
    __shared__ float zw1_s[NN];
    __shared__ int nonuniform;

    const int tid  = threadIdx.x;
    const int wid  = tid >> 5;
    const int lane = tid & 31;
    const int warps_per_block = blockDim.x >> 5;                 // 8
    const int blocks_per_b    = MM / 8;                          // 64
    const int b = blockIdx.x / blocks_per_b;
    const int m = (blockIdx.x % blocks_per_b) * warps_per_block + wid;

    if (tid == 0) nonuniform = 0;
    __syncthreads();

    const float s0 = sigma[0];
    if (tid < ZDIM) {
        if (sigma[tid] != s0) atomicOr(&nonuniform, 1);
    }

    // Stage t[b,:] and zw[b,:,:] into shared
    for (int i = tid; i < NN; i += blockDim.x) {
        t_s[i]   = t[b * NN + i];                 // XD == 1
        zw0_s[i] = g_zw[(b * NN + i) * YDIM + 0];
        zw1_s[i] = g_zw[(b * NN + i) * YDIM + 1];
    }
    __syncthreads();

    const float xm = x[b * MM + m];               // XD == 1
    float a0 = 0.0f, a1 = 0.0f;

    if (!nonuniform) {
        // ---- fast path: exp factors out of the channel sum ----
        const float coef = -0.5f * __expf(-2.0f * s0);
#pragma unroll 4
        for (int i = lane; i < NN; i += 32) {
            float d = xm - t_s[i];
            float e = __expf(coef * d * d);
            a0 = fmaf(e, zw0_s[i], a0);
            a1 = fmaf(e, zw1_s[i], a1);
        }
    } else {
        // ---- general path: per-channel RBF scale ----
        for (int i = 0; i < NN; ++i) {
            float d  = xm - t_s[i];
            float d2 = d * d;
            const float* zr = z + (b * NN + i) * ZDIM;
#pragma unroll
            for (int j = 0; j < ZDIM / 32; ++j) {
                int   c   = lane + 32 * j;
                float sc  = __expf(sigma[c]);
                float inv = 1.0f / sc;
                float e   = __expf(-0.5f * d2 * inv * inv);
                float zk  = zr[c] * e;
                a0 = fmaf(zk, W[0 * ZDIM + c], a0);
                a1 = fmaf(zk, W[1 * ZDIM + c], a1);
            }
        }
    }

    // warp-level tree reduction
#pragma unroll
    for (int o = 16; o; o >>= 1) {
        a0 += __shfl_xor_sync(0xFFFFFFFFu, a0, o);
        a1 += __shfl_xor_sync(0xFFFFFFFFu, a1, o);
    }
    if (lane == 0) {
        out[(b * MM + m) * YDIM + 0] = a0 + bias[0];
        out[(b * MM + m) * YDIM + 1] = a1 + bias[1];
    }
}

// ---------------------------------------------------------------------------
extern "C" void kernel_launch(void* const* d_in, const int* in_sizes, int n_in,
                              void* d_out, int out_size) {
    const float* t     = (const float*)d_in[0];
    const float* z     = (const float*)d_in[1];
    const float* x     = (const float*)d_in[2];
    const float* sigma = (const float*)d_in[3];
    const float* W     = (const float*)d_in[4];
    const float* bias  = (const float*)d_in[5];
    float* out = (float*)d_out;

    prep_zw_kernel<<<(BB * NN * YDIM + 255) / 256, 256>>>(z, W);
    decoder_main_kernel<<<BB * (MM / 8), 256>>>(t, z, x, sigma, W, bias, out);
}